// round 1
// baseline (speedup 1.0000x reference)
#include <cuda_runtime.h>
#include <math.h>

#define BATCH 128

// ----------------- scratch buffers (device globals; no mallocs allowed) -----------------
__device__ float d_c1[BATCH*96*55*55];
__device__ float d_p1[BATCH*96*27*27];
__device__ float d_l1[BATCH*96*27*27];
__device__ float d_c2[BATCH*256*27*27];
__device__ float d_p2[BATCH*256*13*13];
__device__ float d_l2[BATCH*256*13*13];
__device__ float d_c3[BATCH*384*13*13];
__device__ float d_c4[BATCH*384*13*13];
__device__ float d_c5[BATCH*256*13*13];
__device__ float d_feat[BATCH*9216];
__device__ float d_h1[BATCH*4096];
__device__ float d_h2[BATCH*4096];
__device__ float d_out0[BATCH*100];
__device__ float d_g2[BATCH*4096];
__device__ float d_g1[BATCH*4096];
__device__ float d_gf[BATCH*9216];
__device__ float d_sm[BATCH*36];
__device__ float d_mask[BATCH*36];
__device__ float d_maskf[BATCH*36];
__device__ float d_featm[BATCH*9216];
__device__ float d_h1b[BATCH*4096];
__device__ float d_h2b[BATCH*4096];
__device__ float d_outb[BATCH*100];
__device__ float d_clsb[BATCH];
__device__ float d_clsa[BATCH];
__device__ float d_featf[BATCH*9216];
__device__ float d_h1c[BATCH*4096];
__device__ float d_h2c[BATCH*4096];

// ----------------- implicit-GEMM direct convolution -----------------
// C[oc, (n,oh,ow)] = sum_k W[oc,k] * im2col(x)[k,(n,oh,ow)]  + bias, ReLU
// Tile: 128(M=oc) x 128(N=pixels) x 8(K), 256 threads, 8x8 microtile (strided by 16)
template<int CING, int HH, int WW, int COUTG, int COUTT, int KH, int KW,
         int STR, int PAD, int OH, int OW, int GROUPS>
__global__ __launch_bounds__(256)
void conv_kernel(const float* __restrict__ x, const float* __restrict__ w,
                 const float* __restrict__ bias, float* __restrict__ out, float scale)
{
    constexpr int K    = CING*KH*KW;
    constexpr int NPIX = BATCH*OH*OW;
    constexpr int CINT = CING*GROUPS;
    constexpr int OHW  = OH*OW;

    const int g    = blockIdx.z;
    const int pix0 = blockIdx.x * 128;
    const int m0   = blockIdx.y * 128;

    __shared__ float As[128][9];
    __shared__ float Bs[128][9];

    const int t    = threadIdx.x;
    const int tx   = t & 15;
    const int ty   = t >> 4;
    const int lk   = t & 7;     // k-lane for loading
    const int lrow = t >> 3;    // 0..31 row base for loading

    // pixel decode (fixed per thread across the k-loop)
    int ihb[4], iwb[4], xb[4], orow[4];
    bool pvld[4];
    #pragma unroll
    for (int p = 0; p < 4; ++p) {
        int pix = pix0 + lrow + p*32;
        pvld[p] = (pix < NPIX);
        int pc  = pvld[p] ? pix : 0;
        int n   = pc / OHW;
        int rem = pc % OHW;
        int oh  = rem / OW, ow = rem % OW;
        ihb[p]  = oh*STR - PAD;
        iwb[p]  = ow*STR - PAD;
        xb[p]   = (n*CINT + g*CING)*HH*WW;
        orow[p] = 0; (void)orow;
    }

    float acc[8][8];
    #pragma unroll
    for (int i = 0; i < 8; ++i)
        #pragma unroll
        for (int j = 0; j < 8; ++j) acc[i][j] = 0.f;

    for (int k0 = 0; k0 < K; k0 += 8) {
        // A tile (weights)
        #pragma unroll
        for (int p = 0; p < 4; ++p) {
            int m  = lrow + p*32;
            int kg = k0 + lk;
            float v = 0.f;
            if ((m0 + m) < COUTG && kg < K)
                v = w[(g*COUTG + m0 + m)*K + kg];
            As[m][lk] = v;
        }
        // B tile (im2col gather)
        {
            int kg = k0 + lk;
            bool kval = kg < K;
            int kc = kval ? kg : 0;
            int ic = kc / (KH*KW);
            int r  = kc % (KH*KW);
            int kh = r / KW, kw = r % KW;
            #pragma unroll
            for (int p = 0; p < 4; ++p) {
                int ih = ihb[p] + kh;
                int iw = iwb[p] + kw;
                float v = 0.f;
                if (kval && pvld[p] && (unsigned)ih < (unsigned)HH && (unsigned)iw < (unsigned)WW)
                    v = x[xb[p] + ic*HH*WW + ih*WW + iw] * scale;
                Bs[lrow + p*32][lk] = v;
            }
        }
        __syncthreads();
        #pragma unroll
        for (int kk = 0; kk < 8; ++kk) {
            float a[8], bb[8];
            #pragma unroll
            for (int i = 0; i < 8; ++i) a[i]  = As[ty + i*16][kk];
            #pragma unroll
            for (int j = 0; j < 8; ++j) bb[j] = Bs[tx + j*16][kk];
            #pragma unroll
            for (int i = 0; i < 8; ++i)
                #pragma unroll
                for (int j = 0; j < 8; ++j)
                    acc[i][j] = fmaf(a[i], bb[j], acc[i][j]);
        }
        __syncthreads();
    }

    #pragma unroll
    for (int i = 0; i < 8; ++i) {
        int m = m0 + ty + i*16;
        if (m >= COUTG) continue;
        float bv = bias[g*COUTG + m];
        #pragma unroll
        for (int j = 0; j < 8; ++j) {
            int pix = pix0 + tx + j*16;
            if (pix >= NPIX) continue;
            int n   = pix / OHW;
            int rem = pix % OHW;
            float v = fmaxf(acc[i][j] + bv, 0.f);
            out[(n*COUTT + g*COUTG + m)*OHW + rem] = v;
        }
    }
}

// ----------------- maxpool 3x3 stride 2 -----------------
template<int C, int HI, int HO>
__global__ void pool_kernel(const float* __restrict__ in, float* __restrict__ out)
{
    constexpr int TOT = BATCH*C*HO*HO;
    int idx = blockIdx.x*256 + threadIdx.x;
    if (idx >= TOT) return;
    int ox = idx % HO;
    int tq = idx / HO;
    int oy = tq % HO;
    int nc = tq / HO;
    const float* p = in + (nc*HI + oy*2)*HI + ox*2;
    float m = -3.4e38f;
    #pragma unroll
    for (int a = 0; a < 3; ++a)
        #pragma unroll
        for (int b = 0; b < 3; ++b)
            m = fmaxf(m, p[a*HI + b]);
    out[idx] = m;
}

// ----------------- LRN (n=5, alpha=1e-4, beta=0.75, k=1) -----------------
template<int C, int HW>
__global__ void lrn_kernel(const float* __restrict__ in, float* __restrict__ out)
{
    constexpr int TOT = BATCH*C*HW;
    int idx = blockIdx.x*256 + threadIdx.x;
    if (idx >= TOT) return;
    int s = idx % HW;
    int c = (idx / HW) % C;
    int n = idx / (HW*C);
    const float* base = in + n*C*HW + s;
    float sum = 0.f;
    #pragma unroll
    for (int d = -2; d <= 2; ++d) {
        int cc = c + d;
        if (cc >= 0 && cc < C) {
            float v = base[cc*HW];
            sum = fmaf(v, v, sum);
        }
    }
    out[idx] = in[idx] * powf(fmaf(2e-5f, sum, 1.0f), -0.75f);
}

// ----------------- GEMM nt: C[M,N] = A[M,K] * B[N,K]^T (+bias, relu) -----------------
__global__ __launch_bounds__(256)
void gemm_nt(const float* __restrict__ A, const float* __restrict__ Bm,
             const float* __restrict__ bias, float* __restrict__ C,
             int M, int N, int K, int doRelu)
{
    __shared__ float As[64][17];
    __shared__ float Bs[64][17];
    int m0 = blockIdx.y*64, n0 = blockIdx.x*64;
    int t = threadIdx.x, tx = t & 15, ty = t >> 4;
    int lk = t & 15, lr = t >> 4;
    float acc[4][4] = {{0.f}};
    for (int k0 = 0; k0 < K; k0 += 16) {
        #pragma unroll
        for (int p = 0; p < 4; ++p) {
            int row = lr + p*16;
            int kg  = k0 + lk;
            As[row][lk] = ((m0+row) < M && kg < K) ? A[(m0+row)*K + kg] : 0.f;
            Bs[row][lk] = ((n0+row) < N && kg < K) ? Bm[(n0+row)*K + kg] : 0.f;
        }
        __syncthreads();
        #pragma unroll
        for (int kk = 0; kk < 16; ++kk) {
            float a[4], b[4];
            #pragma unroll
            for (int i = 0; i < 4; ++i) a[i] = As[ty + i*16][kk];
            #pragma unroll
            for (int j = 0; j < 4; ++j) b[j] = Bs[tx + j*16][kk];
            #pragma unroll
            for (int i = 0; i < 4; ++i)
                #pragma unroll
                for (int j = 0; j < 4; ++j)
                    acc[i][j] = fmaf(a[i], b[j], acc[i][j]);
        }
        __syncthreads();
    }
    #pragma unroll
    for (int i = 0; i < 4; ++i) {
        int m = m0 + ty + i*16;
        if (m >= M) continue;
        #pragma unroll
        for (int j = 0; j < 4; ++j) {
            int n = n0 + tx + j*16;
            if (n >= N) continue;
            float v = acc[i][j] + bias[n];
            if (doRelu) v = fmaxf(v, 0.f);
            C[m*N + n] = v;
        }
    }
}

// ----------------- GEMM nn: C[M,N] = A[M,K] * B[K,N], optional relu-mask epilogue -----------------
__global__ __launch_bounds__(256)
void gemm_nn(const float* __restrict__ A, const float* __restrict__ Bm,
             const float* __restrict__ maskT, float* __restrict__ C,
             int M, int N, int K)
{
    __shared__ float As[64][17];
    __shared__ float Bs[64][17];
    int m0 = blockIdx.y*64, n0 = blockIdx.x*64;
    int t = threadIdx.x, tx = t & 15, ty = t >> 4;
    int lk = t & 15, lr = t >> 4;
    int bn = t & 63, bk = t >> 6;
    float acc[4][4] = {{0.f}};
    for (int k0 = 0; k0 < K; k0 += 16) {
        #pragma unroll
        for (int p = 0; p < 4; ++p) {
            int row = lr + p*16;
            int kg  = k0 + lk;
            As[row][lk] = ((m0+row) < M && kg < K) ? A[(m0+row)*K + kg] : 0.f;
            int kb = bk + p*4;
            Bs[bn][kb] = ((k0+kb) < K && (n0+bn) < N) ? Bm[(k0+kb)*N + n0 + bn] : 0.f;
        }
        __syncthreads();
        #pragma unroll
        for (int kk = 0; kk < 16; ++kk) {
            float a[4], b[4];
            #pragma unroll
            for (int i = 0; i < 4; ++i) a[i] = As[ty + i*16][kk];
            #pragma unroll
            for (int j = 0; j < 4; ++j) b[j] = Bs[tx + j*16][kk];
            #pragma unroll
            for (int i = 0; i < 4; ++i)
                #pragma unroll
                for (int j = 0; j < 4; ++j)
                    acc[i][j] = fmaf(a[i], b[j], acc[i][j]);
        }
        __syncthreads();
    }
    #pragma unroll
    for (int i = 0; i < 4; ++i) {
        int m = m0 + ty + i*16;
        if (m >= M) continue;
        #pragma unroll
        for (int j = 0; j < 4; ++j) {
            int n = n0 + tx + j*16;
            if (n >= N) continue;
            float v = acc[i][j];
            if (maskT) v = (maskT[m*N + n] > 0.f) ? v : 0.f;
            C[m*N + n] = v;
        }
    }
}

// ----------------- classifier dot: out[n,c] = h2[n,:].wc[c,:] + bc[c] -----------------
__global__ void cls_kernel(const float* __restrict__ h, const float* __restrict__ wc,
                           const float* __restrict__ bc, float* __restrict__ out)
{
    int n = blockIdx.x;
    int warp = threadIdx.x >> 5, lane = threadIdx.x & 31;
    int c = blockIdx.y*8 + warp;
    if (c >= 100) return;
    const float4* hp = (const float4*)(h + n*4096);
    const float4* wp = (const float4*)(wc + c*4096);
    float s = 0.f;
    for (int k = lane; k < 1024; k += 32) {
        float4 a = hp[k], b = wp[k];
        s += a.x*b.x + a.y*b.y + a.z*b.z + a.w*b.w;
    }
    #pragma unroll
    for (int o = 16; o; o >>= 1) s += __shfl_xor_sync(0xffffffffu, s, o);
    if (lane == 0) out[n*100 + c] = s + bc[c];
}

// ----------------- softmax probability at gt -----------------
__global__ void softgt_kernel(const float* __restrict__ logits, const int* __restrict__ gt,
                              float* __restrict__ cls)
{
    int n = blockIdx.x;
    int lane = threadIdx.x;
    float m = -3.4e38f;
    for (int c = lane; c < 100; c += 32) m = fmaxf(m, logits[n*100 + c]);
    #pragma unroll
    for (int o = 16; o; o >>= 1) m = fmaxf(m, __shfl_xor_sync(0xffffffffu, m, o));
    float s = 0.f;
    for (int c = lane; c < 100; c += 32) s += expf(logits[n*100 + c] - m);
    #pragma unroll
    for (int o = 16; o; o >>= 1) s += __shfl_xor_sync(0xffffffffu, s, o);
    if (lane == 0) cls[n] = expf(logits[n*100 + gt[n]] - m) / s;
}

// ----------------- g2m: grad at h2-pre = relu'(h2) * wc[gt] -----------------
__global__ void g2m_kernel(const float* __restrict__ h2, const float* __restrict__ wc,
                           const int* __restrict__ gt, float* __restrict__ g2)
{
    int idx = blockIdx.x*256 + threadIdx.x;
    if (idx >= BATCH*4096) return;
    int n = idx >> 12, j = idx & 4095;
    g2[idx] = (h2[idx] > 0.f) ? wc[gt[n]*4096 + j] : 0.f;
}

// ----------------- spatial mean over 256 channels -----------------
__global__ void smean_kernel(const float* __restrict__ gf, float* __restrict__ sm)
{
    int n = blockIdx.x, s = threadIdx.x;
    if (s >= 36) return;
    const float* p = gf + n*9216 + s;
    float acc = 0.f;
    for (int c = 0; c < 256; ++c) acc += p[c*36];
    sm[n*36 + s] = acc * (1.f/256.f);
}

// ----------------- per-sample RSC spatial mask -----------------
__global__ void mask_kernel(const float* __restrict__ sm, const float* __restrict__ u,
                            const int* __restrict__ flag, float* __restrict__ mask)
{
    int n = threadIdx.x;
    if (n >= BATCH) return;
    if (*flag == 0) {
        for (int s = 0; s < 36; ++s) mask[n*36 + s] = 1.f;
        return;
    }
    float v[36], tmp[36], sc[36], mk[36];
    for (int s = 0; s < 36; ++s) { v[s] = sm[n*36 + s]; tmp[s] = v[s]; mk[s] = 1.f; }
    // 13th largest (descending-sorted index 12)
    float th = 0.f;
    for (int it = 0; it < 13; ++it) {
        int bi = 0; float bv = tmp[0];
        for (int s = 1; s < 36; ++s) if (tmp[s] > bv) { bv = tmp[s]; bi = s; }
        th = bv; tmp[bi] = -3.4e38f;
    }
    for (int s = 0; s < 36; ++s) sc[s] = (v[s] >= th) ? u[n*36 + s] : -1.f;
    // drop the 12 candidates with largest u
    for (int it = 0; it < 12; ++it) {
        int bi = 0; float bv = sc[0];
        for (int s = 1; s < 36; ++s) if (sc[s] > bv) { bv = sc[s]; bi = s; }
        mk[bi] = 0.f; sc[bi] = -2.f;
    }
    for (int s = 0; s < 36; ++s) mask[n*36 + s] = mk[s];
}

// ----------------- keep decision (cv ranking) + final mask -----------------
__global__ void keep_kernel(const float* __restrict__ clsb, const float* __restrict__ clsa,
                            const float* __restrict__ mask, float* __restrict__ maskf)
{
    __shared__ float cv[BATCH];
    __shared__ float thf;
    int n = threadIdx.x;
    cv[n] = fmaxf(clsb[n] - clsa[n] - 1e-4f, 0.f);
    __syncthreads();
    if (n == 0) {
        float tmp[BATCH];
        for (int i = 0; i < BATCH; ++i) tmp[i] = cv[i];
        float bv = 0.f;
        for (int it = 0; it < 44; ++it) {   // descending index 43 = round(128/3)
            int bi = 0; bv = tmp[0];
            for (int i = 1; i < BATCH; ++i) if (tmp[i] > bv) { bv = tmp[i]; bi = i; }
            tmp[bi] = -3.4e38f;
        }
        thf = bv;
    }
    __syncthreads();
    bool keep = !(cv[n] > thf);
    for (int s = 0; s < 36; ++s)
        maskf[n*36 + s] = keep ? 1.f : mask[n*36 + s];
}

// ----------------- apply spatial mask to features -----------------
__global__ void applymask_kernel(const float* __restrict__ f, const float* __restrict__ mask,
                                 float* __restrict__ o)
{
    int i = blockIdx.x*256 + threadIdx.x;
    if (i >= BATCH*9216) return;
    int n = i / 9216;
    int s = i % 36;
    o[i] = f[i] * mask[n*36 + s];
}

// ----------------- launch -----------------
static float* sym(const void* symbol)
{
    void* p = nullptr;
    cudaGetSymbolAddress(&p, symbol);
    return (float*)p;
}

extern "C" void kernel_launch(void* const* d_in, const int* in_sizes, int n_in,
                              void* d_out, int out_size)
{
    const float* x    = (const float*)d_in[0];
    const int*   gt   = (const int*)  d_in[1];
    const float* u    = (const float*)d_in[2];
    const int*   flag = (const int*)  d_in[3];
    const float* w1 = (const float*)d_in[4];  const float* b1 = (const float*)d_in[5];
    const float* w2 = (const float*)d_in[6];  const float* b2 = (const float*)d_in[7];
    const float* w3 = (const float*)d_in[8];  const float* b3 = (const float*)d_in[9];
    const float* w4 = (const float*)d_in[10]; const float* b4 = (const float*)d_in[11];
    const float* w5 = (const float*)d_in[12]; const float* b5 = (const float*)d_in[13];
    const float* w6 = (const float*)d_in[14]; const float* b6 = (const float*)d_in[15];
    const float* w7 = (const float*)d_in[16]; const float* b7 = (const float*)d_in[17];
    const float* wc = (const float*)d_in[18]; const float* bc = (const float*)d_in[19];
    float* out = (float*)d_out;

    float* c1   = sym(d_c1);   float* p1   = sym(d_p1);   float* l1   = sym(d_l1);
    float* c2   = sym(d_c2);   float* p2   = sym(d_p2);   float* l2   = sym(d_l2);
    float* c3   = sym(d_c3);   float* c4   = sym(d_c4);   float* c5   = sym(d_c5);
    float* feat = sym(d_feat);
    float* h1   = sym(d_h1);   float* h2   = sym(d_h2);   float* out0 = sym(d_out0);
    float* g2   = sym(d_g2);   float* g1   = sym(d_g1);   float* gf   = sym(d_gf);
    float* smv  = sym(d_sm);   float* mask = sym(d_mask); float* maskf= sym(d_maskf);
    float* featm= sym(d_featm);float* h1b  = sym(d_h1b);  float* h2b  = sym(d_h2b);
    float* outb = sym(d_outb); float* clsb = sym(d_clsb); float* clsa = sym(d_clsa);
    float* featf= sym(d_featf);float* h1c  = sym(d_h1c);  float* h2c  = sym(d_h2c);

    // ---- feature extractor ----
    conv_kernel<3,227,227,96,96,11,11,4,0,55,55,1><<<dim3(3025,1,1),256>>>(x, w1, b1, c1, 57.6f);
    pool_kernel<96,55,27><<<34992,256>>>(c1, p1);
    lrn_kernel<96,729><<<34992,256>>>(p1, l1);
    conv_kernel<48,27,27,128,256,5,5,1,2,27,27,2><<<dim3(729,1,2),256>>>(l1, w2, b2, c2, 1.f);
    pool_kernel<256,27,13><<<21632,256>>>(c2, p2);
    lrn_kernel<256,169><<<21632,256>>>(p2, l2);
    conv_kernel<256,13,13,384,384,3,3,1,1,13,13,1><<<dim3(169,3,1),256>>>(l2, w3, b3, c3, 1.f);
    conv_kernel<192,13,13,192,384,3,3,1,1,13,13,2><<<dim3(169,2,2),256>>>(c3, w4, b4, c4, 1.f);
    conv_kernel<192,13,13,128,256,3,3,1,1,13,13,2><<<dim3(169,1,2),256>>>(c4, w5, b5, c5, 1.f);
    pool_kernel<256,13,6><<<4608,256>>>(c5, feat);

    // ---- head #1 (unmasked) ----
    gemm_nt<<<dim3(64,2),256>>>(feat, w6, b6, h1, 128, 4096, 9216, 1);
    gemm_nt<<<dim3(64,2),256>>>(h1,   w7, b7, h2, 128, 4096, 4096, 1);
    cls_kernel<<<dim3(128,13),256>>>(h2, wc, bc, out0);
    softgt_kernel<<<128,32>>>(out0, gt, clsb);

    // ---- analytic gradient of out[n,gt] wrt features ----
    g2m_kernel<<<2048,256>>>(h2, wc, gt, g2);
    gemm_nn<<<dim3(64,2),256>>>(g2, w7, h1, g1, 128, 4096, 4096);
    gemm_nn<<<dim3(144,2),256>>>(g1, w6, nullptr, gf, 128, 9216, 4096);
    smean_kernel<<<128,64>>>(gf, smv);

    // ---- RSC spatial mask ----
    mask_kernel<<<1,128>>>(smv, u, flag, mask);
    applymask_kernel<<<4608,256>>>(feat, mask, featm);

    // ---- head #2 (masked) ----
    gemm_nt<<<dim3(64,2),256>>>(featm, w6, b6, h1b, 128, 4096, 9216, 1);
    gemm_nt<<<dim3(64,2),256>>>(h1b,   w7, b7, h2b, 128, 4096, 4096, 1);
    cls_kernel<<<dim3(128,13),256>>>(h2b, wc, bc, outb);
    softgt_kernel<<<128,32>>>(outb, gt, clsa);

    // ---- keep decision + final mask ----
    keep_kernel<<<1,128>>>(clsb, clsa, mask, maskf);
    applymask_kernel<<<4608,256>>>(feat, maskf, featf);

    // ---- head #3 (final output) ----
    gemm_nt<<<dim3(64,2),256>>>(featf, w6, b6, h1c, 128, 4096, 9216, 1);
    gemm_nt<<<dim3(64,2),256>>>(h1c,   w7, b7, h2c, 128, 4096, 4096, 1);
    cls_kernel<<<dim3(128,13),256>>>(h2c, wc, bc, out);

    (void)in_sizes; (void)n_in; (void)out_size;
}

// round 2
// speedup vs baseline: 1.7663x; 1.7663x over previous
#include <cuda_runtime.h>
#include <math.h>
#include <stdint.h>

#define BATCH 128

// ----------------- scratch buffers -----------------
__device__ float d_c1[BATCH*96*55*55];
__device__ float d_p1[BATCH*96*27*27];
__device__ float d_l1[BATCH*96*27*27];
__device__ float d_c2[BATCH*256*27*27];
__device__ float d_p2[BATCH*256*13*13];
__device__ float d_l2[BATCH*256*13*13];
__device__ float d_c3[BATCH*384*13*13];
__device__ float d_c4[BATCH*384*13*13];
__device__ float d_c5[BATCH*256*13*13];
__device__ float d_feat[BATCH*9216];
__device__ float d_h1[BATCH*4096];
__device__ float d_h2[BATCH*4096];
__device__ float d_out0[BATCH*100];
__device__ float d_g2[BATCH*4096];
__device__ float d_g1[BATCH*4096];
__device__ float d_sm[BATCH*36];
__device__ float d_mask[BATCH*36];
__device__ float d_featm[BATCH*9216];
__device__ float d_h1b[BATCH*4096];
__device__ float d_h2b[BATCH*4096];
__device__ float d_outb[BATCH*100];
__device__ float d_clsb[BATCH];
__device__ float d_clsa[BATCH];
__device__ float d_w6r[4096*36];
__device__ float d_part[8*BATCH*4096];

// ----------------- f32x2 helpers -----------------
__device__ __forceinline__ unsigned long long pack2(float a, float b) {
    unsigned long long r;
    asm("mov.b64 %0, {%1, %2};" : "=l"(r) : "r"(__float_as_uint(a)), "r"(__float_as_uint(b)));
    return r;
}
__device__ __forceinline__ void fma2(unsigned long long& d, unsigned long long a, unsigned long long b) {
    asm("fma.rn.f32x2 %0, %1, %2, %0;" : "+l"(d) : "l"(a), "l"(b));
}
__device__ __forceinline__ float2 unpack2(unsigned long long v) {
    unsigned lo, hi;
    asm("mov.b64 {%0, %1}, %2;" : "=r"(lo), "=r"(hi) : "l"(v));
    float2 f; f.x = __uint_as_float(lo); f.y = __uint_as_float(hi); return f;
}

// ----------------- implicit-GEMM conv, f32x2, double-buffered -----------------
// Tile: MT(oc) x 128(pixels) x 16(K). 256 threads. micro: (MT/16) x 8 (4 float2 pairs).
template<int CING, int HH, int WW, int COUTG, int COUTT, int KH, int KW,
         int STR, int PAD, int OH, int OW, int GROUPS, int MT>
__global__ __launch_bounds__(256, 2)
void conv_f2(const float* __restrict__ x, const float* __restrict__ w,
             const float* __restrict__ bias, float* __restrict__ out, float scale)
{
    constexpr int K    = CING*KH*KW;
    constexpr int CINT = CING*GROUPS;
    constexpr int OHW  = OH*OW;
    constexpr int MI   = MT/16;
    constexpr int AS   = MT + 4;
    constexpr int NCH  = (K + 15)/16;

    const int g    = blockIdx.z;
    const int pix0 = blockIdx.x * 128;
    const int m0   = blockIdx.y * MT;

    __shared__ __align__(16) float As[2][16][AS];
    __shared__ __align__(16) float Bs[2][16][132];

    const int t  = threadIdx.x;
    const int tx = t & 15, ty = t >> 4;
    const int lk = t & 15, lr = t >> 4;

    int ihb[8], iwb[8], xb[8];
    #pragma unroll
    for (int p = 0; p < 8; ++p) {
        int pix = pix0 + lr + p*16;
        int n   = pix / OHW; int rem = pix - n*OHW;
        int oh  = rem / OW;  int ow  = rem - oh*OW;
        ihb[p] = oh*STR - PAD; iwb[p] = ow*STR - PAD;
        xb[p]  = (n*CINT + g*CING)*HH*WW;
    }

    const float* wbase = w + (size_t)(g*COUTG + m0)*K;

    float ra[MI], rb[8];

    auto loadA = [&](int k0) {
        int kg = k0 + lk; bool kv = kg < K;
        #pragma unroll
        for (int p = 0; p < MI; ++p)
            ra[p] = kv ? wbase[(lr + p*16)*K + kg] : 0.f;
    };
    auto loadB = [&](int k0) {
        int kg = k0 + lk; bool kv = kg < K;
        int kc = kv ? kg : 0;
        int ic = kc / (KH*KW);
        int r2 = kc - ic*(KH*KW);
        int kh = r2 / KW, kw = r2 - kh*KW;
        #pragma unroll
        for (int p = 0; p < 8; ++p) {
            int ih = ihb[p] + kh, iw = iwb[p] + kw;
            float v = 0.f;
            if (kv && (unsigned)ih < (unsigned)HH && (unsigned)iw < (unsigned)WW)
                v = x[xb[p] + ic*HH*WW + ih*WW + iw] * scale;
            rb[p] = v;
        }
    };
    auto stTile = [&](int buf) {
        #pragma unroll
        for (int p = 0; p < MI; ++p) As[buf][lk][lr + p*16] = ra[p];
        #pragma unroll
        for (int p = 0; p < 8;  ++p) Bs[buf][lk][lr + p*16] = rb[p];
    };

    unsigned long long acc[MI][4];
    #pragma unroll
    for (int i = 0; i < MI; ++i)
        #pragma unroll
        for (int j = 0; j < 4; ++j) acc[i][j] = 0ull;

    loadA(0); loadB(0); stTile(0);
    __syncthreads();

    for (int c = 0; c < NCH; ++c) {
        int buf = c & 1;
        if (c + 1 < NCH) { loadA((c+1)*16); loadB((c+1)*16); }
        #pragma unroll
        for (int kk = 0; kk < 16; ++kk) {
            unsigned long long b2[4];
            #pragma unroll
            for (int j = 0; j < 4; ++j)
                b2[j] = *(const unsigned long long*)&Bs[buf][kk][tx*2 + j*32];
            #pragma unroll
            for (int i = 0; i < MI; ++i) {
                float av = As[buf][kk][ty + i*16];
                unsigned long long a2 = pack2(av, av);
                #pragma unroll
                for (int j = 0; j < 4; ++j) fma2(acc[i][j], a2, b2[j]);
            }
        }
        if (c + 1 < NCH) stTile(buf ^ 1);
        __syncthreads();
    }

    #pragma unroll
    for (int i = 0; i < MI; ++i) {
        int m = m0 + ty + i*16;
        float bv = bias[g*COUTG + m];
        #pragma unroll
        for (int j = 0; j < 4; ++j) {
            float2 v = unpack2(acc[i][j]);
            int pix = pix0 + tx*2 + j*32;
            int n0_ = pix / OHW;       int r0_ = pix - n0_*OHW;
            int n1_ = (pix+1) / OHW;   int r1_ = (pix+1) - n1_*OHW;
            out[((size_t)(n0_*COUTT + g*COUTG + m))*OHW + r0_] = fmaxf(v.x + bv, 0.f);
            out[((size_t)(n1_*COUTT + g*COUTG + m))*OHW + r1_] = fmaxf(v.y + bv, 0.f);
        }
    }
}

// ----------------- maxpool 3x3 stride 2 -----------------
template<int C, int HI, int HO>
__global__ void pool_kernel(const float* __restrict__ in, float* __restrict__ out)
{
    constexpr int TOT = BATCH*C*HO*HO;
    int idx = blockIdx.x*256 + threadIdx.x;
    if (idx >= TOT) return;
    int ox = idx % HO;
    int tq = idx / HO;
    int oy = tq % HO;
    int nc = tq / HO;
    const float* p = in + (nc*HI + oy*2)*HI + ox*2;
    float m = -3.4e38f;
    #pragma unroll
    for (int a = 0; a < 3; ++a)
        #pragma unroll
        for (int b = 0; b < 3; ++b)
            m = fmaxf(m, p[a*HI + b]);
    out[idx] = m;
}

// ----------------- LRN -----------------
template<int C, int HW>
__global__ void lrn_kernel(const float* __restrict__ in, float* __restrict__ out)
{
    constexpr int TOT = BATCH*C*HW;
    int idx = blockIdx.x*256 + threadIdx.x;
    if (idx >= TOT) return;
    int s = idx % HW;
    int c = (idx / HW) % C;
    int n = idx / (HW*C);
    const float* base = in + n*C*HW + s;
    float sum = 0.f;
    #pragma unroll
    for (int d = -2; d <= 2; ++d) {
        int cc = c + d;
        if (cc >= 0 && cc < C) {
            float v = base[cc*HW];
            sum = fmaf(v, v, sum);
        }
    }
    float r = rsqrtf(fmaf(2e-5f, sum, 1.0f));      // (1+a s)^-0.5
    out[idx] = in[idx] * r * sqrtf(r);             // ^-0.75
}

// ----------------- split-K GEMM, f32x2, 64x64 tiles -----------------
// C_part[z][M,N] = A[M, kchunk] * B  (nt: B[N,K]; nn: B[K,N])
template<int TRANSB>
__global__ __launch_bounds__(256, 2)
void gemm_f2(const float* __restrict__ A, const float* __restrict__ B,
             float* __restrict__ part, int M, int N, int K, int Kc)
{
    __shared__ __align__(16) float As[2][16][68];
    __shared__ __align__(16) float Bs[2][16][68];
    const int m0 = blockIdx.y*64, n0 = blockIdx.x*64;
    const int z  = blockIdx.z;
    const int kb = z*Kc;
    const int ke = min(K, kb + Kc);
    const int t = threadIdx.x, tx = t & 15, ty = t >> 4;
    const int lk = t & 15, lr = t >> 4;
    const int lr2 = t & 63, lk2 = t >> 6;

    float ra[4], rbv[4];
    auto loadA = [&](int k0) {
        int kg = k0 + lk; bool kv = kg < ke;
        #pragma unroll
        for (int p = 0; p < 4; ++p)
            ra[p] = kv ? A[(size_t)(m0 + lr + p*16)*K + kg] : 0.f;
    };
    auto loadB = [&](int k0) {
        if (TRANSB) {
            int kg = k0 + lk; bool kv = kg < ke;
            #pragma unroll
            for (int p = 0; p < 4; ++p)
                rbv[p] = kv ? B[(size_t)(n0 + lr + p*16)*K + kg] : 0.f;
        } else {
            #pragma unroll
            for (int p = 0; p < 4; ++p) {
                int kg = k0 + lk2 + p*4;
                rbv[p] = (kg < ke) ? B[(size_t)kg*N + n0 + lr2] : 0.f;
            }
        }
    };
    auto stT = [&](int buf) {
        #pragma unroll
        for (int p = 0; p < 4; ++p) As[buf][lk][lr + p*16] = ra[p];
        if (TRANSB) {
            #pragma unroll
            for (int p = 0; p < 4; ++p) Bs[buf][lk][lr + p*16] = rbv[p];
        } else {
            #pragma unroll
            for (int p = 0; p < 4; ++p) Bs[buf][lk2 + p*4][lr2] = rbv[p];
        }
    };

    unsigned long long acc[4][2];
    #pragma unroll
    for (int i = 0; i < 4; ++i) { acc[i][0] = 0ull; acc[i][1] = 0ull; }

    const int nch = (ke - kb + 15)/16;
    loadA(kb); loadB(kb); stT(0);
    __syncthreads();

    for (int c = 0; c < nch; ++c) {
        int buf = c & 1;
        if (c + 1 < nch) { loadA(kb + (c+1)*16); loadB(kb + (c+1)*16); }
        #pragma unroll
        for (int kk = 0; kk < 16; ++kk) {
            unsigned long long b2[2];
            #pragma unroll
            for (int j = 0; j < 2; ++j)
                b2[j] = *(const unsigned long long*)&Bs[buf][kk][tx*2 + j*32];
            #pragma unroll
            for (int i = 0; i < 4; ++i) {
                float av = As[buf][kk][ty + i*16];
                unsigned long long a2 = pack2(av, av);
                #pragma unroll
                for (int j = 0; j < 2; ++j) fma2(acc[i][j], a2, b2[j]);
            }
        }
        if (c + 1 < nch) stT(buf ^ 1);
        __syncthreads();
    }

    #pragma unroll
    for (int i = 0; i < 4; ++i) {
        int m = m0 + ty + i*16;
        #pragma unroll
        for (int j = 0; j < 2; ++j) {
            float2 v = unpack2(acc[i][j]);
            int n = n0 + tx*2 + j*32;
            *(float2*)&part[((size_t)z*M + m)*N + n] = v;
        }
    }
}

// ----------------- split-K reduce + bias/relu/mask epilogue (N=4096) -----------------
__global__ void reduce_k(const float* __restrict__ part, const float* __restrict__ bias,
                         const float* __restrict__ maskref, float* __restrict__ C,
                         int MN, int S, int doRelu)
{
    int i = blockIdx.x*256 + threadIdx.x;
    if (i >= MN) return;
    float s = 0.f;
    for (int z = 0; z < S; ++z) s += part[(size_t)z*MN + i];
    if (bias) s += bias[i & 4095];
    if (doRelu) s = fmaxf(s, 0.f);
    if (maskref) s = (maskref[i] > 0.f) ? s : 0.f;
    C[i] = s;
}

// ----------------- fold w6 over channels: w6r[j,s] = mean_c w6[j, c*36+s] -----------------
__global__ void w6fold_k(const float* __restrict__ w6, float* __restrict__ w6r)
{
    int i = blockIdx.x*256 + threadIdx.x;
    if (i >= 4096*36) return;
    int j = i / 36, s = i - j*36;
    const float* p = w6 + (size_t)j*9216 + s;
    float acc = 0.f;
    for (int c = 0; c < 256; ++c) acc += p[c*36];
    w6r[i] = acc * (1.f/256.f);
}

// ----------------- sm[n,s] = g1[n,:] . w6r[:,s] -----------------
__global__ void smgemm_k(const float* __restrict__ g1, const float* __restrict__ w6r,
                         float* __restrict__ sm)
{
    __shared__ float gs[4096];
    int n = blockIdx.x, t = threadIdx.x;
    for (int k = t; k < 4096; k += 256) gs[k] = g1[n*4096 + k];
    __syncthreads();
    int warp = t >> 5, lane = t & 31;
    for (int s = warp; s < 36; s += 8) {
        float acc = 0.f;
        for (int k = lane; k < 4096; k += 32) acc += gs[k] * w6r[k*36 + s];
        #pragma unroll
        for (int o = 16; o; o >>= 1) acc += __shfl_xor_sync(0xffffffffu, acc, o);
        if (lane == 0) sm[n*36 + s] = acc;
    }
}

// ----------------- classifier dot -----------------
__global__ void cls_kernel(const float* __restrict__ h, const float* __restrict__ wc,
                           const float* __restrict__ bc, float* __restrict__ out)
{
    int n = blockIdx.x;
    int warp = threadIdx.x >> 5, lane = threadIdx.x & 31;
    int c = blockIdx.y*8 + warp;
    if (c >= 100) return;
    const float4* hp = (const float4*)(h + n*4096);
    const float4* wp = (const float4*)(wc + c*4096);
    float s = 0.f;
    for (int k = lane; k < 1024; k += 32) {
        float4 a = hp[k], b = wp[k];
        s += a.x*b.x + a.y*b.y + a.z*b.z + a.w*b.w;
    }
    #pragma unroll
    for (int o = 16; o; o >>= 1) s += __shfl_xor_sync(0xffffffffu, s, o);
    if (lane == 0) out[n*100 + c] = s + bc[c];
}

// ----------------- softmax probability at gt -----------------
__global__ void softgt_kernel(const float* __restrict__ logits, const int* __restrict__ gt,
                              float* __restrict__ cls)
{
    int n = blockIdx.x;
    int lane = threadIdx.x;
    float m = -3.4e38f;
    for (int c = lane; c < 100; c += 32) m = fmaxf(m, logits[n*100 + c]);
    #pragma unroll
    for (int o = 16; o; o >>= 1) m = fmaxf(m, __shfl_xor_sync(0xffffffffu, m, o));
    float s = 0.f;
    for (int c = lane; c < 100; c += 32) s += expf(logits[n*100 + c] - m);
    #pragma unroll
    for (int o = 16; o; o >>= 1) s += __shfl_xor_sync(0xffffffffu, s, o);
    if (lane == 0) cls[n] = expf(logits[n*100 + gt[n]] - m) / s;
}

// ----------------- g2 = relu'(h2) * wc[gt] -----------------
__global__ void g2m_kernel(const float* __restrict__ h2, const float* __restrict__ wc,
                           const int* __restrict__ gt, float* __restrict__ g2)
{
    int idx = blockIdx.x*256 + threadIdx.x;
    if (idx >= BATCH*4096) return;
    int n = idx >> 12, j = idx & 4095;
    g2[idx] = (h2[idx] > 0.f) ? wc[gt[n]*4096 + j] : 0.f;
}

// ----------------- per-sample RSC spatial mask -----------------
__global__ void mask_kernel(const float* __restrict__ sm, const float* __restrict__ u,
                            const int* __restrict__ flag, float* __restrict__ mask)
{
    int n = threadIdx.x;
    if (n >= BATCH) return;
    if (*flag == 0) {
        for (int s = 0; s < 36; ++s) mask[n*36 + s] = 1.f;
        return;
    }
    float v[36], tmp[36], sc[36], mk[36];
    for (int s = 0; s < 36; ++s) { v[s] = sm[n*36 + s]; tmp[s] = v[s]; mk[s] = 1.f; }
    float th = 0.f;
    for (int it = 0; it < 13; ++it) {
        int bi = 0; float bv = tmp[0];
        for (int s = 1; s < 36; ++s) if (tmp[s] > bv) { bv = tmp[s]; bi = s; }
        th = bv; tmp[bi] = -3.4e38f;
    }
    for (int s = 0; s < 36; ++s) sc[s] = (v[s] >= th) ? u[n*36 + s] : -1.f;
    for (int it = 0; it < 12; ++it) {
        int bi = 0; float bv = sc[0];
        for (int s = 1; s < 36; ++s) if (sc[s] > bv) { bv = sc[s]; bi = s; }
        mk[bi] = 0.f; sc[bi] = -2.f;
    }
    for (int s = 0; s < 36; ++s) mask[n*36 + s] = mk[s];
}

// ----------------- apply spatial mask -----------------
__global__ void applymask_kernel(const float* __restrict__ f, const float* __restrict__ mask,
                                 float* __restrict__ o)
{
    int i = blockIdx.x*256 + threadIdx.x;
    if (i >= BATCH*9216) return;
    int n = i / 9216;
    int s = i % 36;
    o[i] = f[i] * mask[n*36 + s];
}

// ----------------- keep decision + per-row output select -----------------
__global__ void keepsel_kernel(const float* __restrict__ clsb, const float* __restrict__ clsa,
                               const float* __restrict__ out0, const float* __restrict__ outb,
                               float* __restrict__ out)
{
    __shared__ float cv[BATCH];
    __shared__ float thf;
    int n = threadIdx.x;
    cv[n] = fmaxf(clsb[n] - clsa[n] - 1e-4f, 0.f);
    __syncthreads();
    if (n == 0) {
        float tmp[BATCH];
        for (int i = 0; i < BATCH; ++i) tmp[i] = cv[i];
        float bv = 0.f;
        for (int it = 0; it < 44; ++it) {   // descending index 43 = int(round(128/3))
            int bi = 0; bv = tmp[0];
            for (int i = 1; i < BATCH; ++i) if (tmp[i] > bv) { bv = tmp[i]; bi = i; }
            tmp[bi] = -3.4e38f;
        }
        thf = bv;
    }
    __syncthreads();
    bool keep = !(cv[n] > thf);
    const float* src = keep ? out0 : outb;
    for (int c = 0; c < 100; ++c) out[n*100 + c] = src[n*100 + c];
}

// ----------------- launch -----------------
static float* sym(const void* symbol)
{
    void* p = nullptr;
    cudaGetSymbolAddress(&p, symbol);
    return (float*)p;
}

extern "C" void kernel_launch(void* const* d_in, const int* in_sizes, int n_in,
                              void* d_out, int out_size)
{
    const float* x    = (const float*)d_in[0];
    const int*   gt   = (const int*)  d_in[1];
    const float* u    = (const float*)d_in[2];
    const int*   flag = (const int*)  d_in[3];
    const float* w1 = (const float*)d_in[4];  const float* b1 = (const float*)d_in[5];
    const float* w2 = (const float*)d_in[6];  const float* b2 = (const float*)d_in[7];
    const float* w3 = (const float*)d_in[8];  const float* b3 = (const float*)d_in[9];
    const float* w4 = (const float*)d_in[10]; const float* b4 = (const float*)d_in[11];
    const float* w5 = (const float*)d_in[12]; const float* b5 = (const float*)d_in[13];
    const float* w6 = (const float*)d_in[14]; const float* b6 = (const float*)d_in[15];
    const float* w7 = (const float*)d_in[16]; const float* b7 = (const float*)d_in[17];
    const float* wc = (const float*)d_in[18]; const float* bc = (const float*)d_in[19];
    float* out = (float*)d_out;

    float* c1   = sym(d_c1);   float* p1   = sym(d_p1);   float* l1   = sym(d_l1);
    float* c2   = sym(d_c2);   float* p2   = sym(d_p2);   float* l2   = sym(d_l2);
    float* c3   = sym(d_c3);   float* c4   = sym(d_c4);   float* c5   = sym(d_c5);
    float* feat = sym(d_feat);
    float* h1   = sym(d_h1);   float* h2   = sym(d_h2);   float* out0 = sym(d_out0);
    float* g2   = sym(d_g2);   float* g1   = sym(d_g1);
    float* smv  = sym(d_sm);   float* mask = sym(d_mask);
    float* featm= sym(d_featm);float* h1b  = sym(d_h1b);  float* h2b  = sym(d_h2b);
    float* outb = sym(d_outb); float* clsb = sym(d_clsb); float* clsa = sym(d_clsa);
    float* w6r  = sym(d_w6r);  float* part = sym(d_part);

    const int MN = BATCH*4096;

    // ---- weight fold (for gradient spatial-mean shortcut) ----
    w6fold_k<<<(4096*36 + 255)/256, 256>>>(w6, w6r);

    // ---- feature extractor ----
    conv_f2<3,227,227,96,96,11,11,4,0,55,55,1,96><<<dim3(3025,1,1),256>>>(x, w1, b1, c1, 57.6f);
    pool_kernel<96,55,27><<<34992,256>>>(c1, p1);
    lrn_kernel<96,729><<<34992,256>>>(p1, l1);
    conv_f2<48,27,27,128,256,5,5,1,2,27,27,2,128><<<dim3(729,1,2),256>>>(l1, w2, b2, c2, 1.f);
    pool_kernel<256,27,13><<<21632,256>>>(c2, p2);
    lrn_kernel<256,169><<<21632,256>>>(p2, l2);
    conv_f2<256,13,13,384,384,3,3,1,1,13,13,1,128><<<dim3(169,3,1),256>>>(l2, w3, b3, c3, 1.f);
    conv_f2<192,13,13,192,384,3,3,1,1,13,13,2,96><<<dim3(169,2,2),256>>>(c3, w4, b4, c4, 1.f);
    conv_f2<192,13,13,128,256,3,3,1,1,13,13,2,128><<<dim3(169,1,2),256>>>(c4, w5, b5, c5, 1.f);
    pool_kernel<256,13,6><<<4608,256>>>(c5, feat);

    // ---- head #1 (unmasked) ----
    gemm_f2<1><<<dim3(64,2,8),256>>>(feat, w6, part, 128, 4096, 9216, 1152);
    reduce_k<<<2048,256>>>(part, b6, nullptr, h1, MN, 8, 1);
    gemm_f2<1><<<dim3(64,2,8),256>>>(h1, w7, part, 128, 4096, 4096, 512);
    reduce_k<<<2048,256>>>(part, b7, nullptr, h2, MN, 8, 1);
    cls_kernel<<<dim3(128,13),256>>>(h2, wc, bc, out0);
    softgt_kernel<<<128,32>>>(out0, gt, clsb);

    // ---- analytic gradient of out[n,gt] wrt features (folded to spatial mean) ----
    g2m_kernel<<<2048,256>>>(h2, wc, gt, g2);
    gemm_f2<0><<<dim3(64,2,8),256>>>(g2, w7, part, 128, 4096, 4096, 512);
    reduce_k<<<2048,256>>>(part, nullptr, h1, g1, MN, 8, 0);
    smgemm_k<<<128,256>>>(g1, w6r, smv);

    // ---- RSC spatial mask ----
    mask_kernel<<<1,128>>>(smv, u, flag, mask);
    applymask_kernel<<<4608,256>>>(feat, mask, featm);

    // ---- head #2 (masked) ----
    gemm_f2<1><<<dim3(64,2,8),256>>>(featm, w6, part, 128, 4096, 9216, 1152);
    reduce_k<<<2048,256>>>(part, b6, nullptr, h1b, MN, 8, 1);
    gemm_f2<1><<<dim3(64,2,8),256>>>(h1b, w7, part, 128, 4096, 4096, 512);
    reduce_k<<<2048,256>>>(part, b7, nullptr, h2b, MN, 8, 1);
    cls_kernel<<<dim3(128,13),256>>>(h2b, wc, bc, outb);
    softgt_kernel<<<128,32>>>(outb, gt, clsa);

    // ---- keep decision + final per-row select (head #3 is row-wise identical to #1/#2) ----
    keepsel_kernel<<<1,128>>>(clsb, clsa, out0, outb, out);

    (void)in_sizes; (void)n_in; (void)out_size;
}